// round 9
// baseline (speedup 1.0000x reference)
#include <cuda_runtime.h>
#include <cuda_bf16.h>
#include <math.h>
#include <stdint.h>

// Problem constants
#define BATCH 2
#define SEQ   2048
#define DIM   2048
#define NH    16
#define HD    128
#define M_TOT (BATCH*SEQ)      // 4096
#define QKV_N (3*DIM)          // 6144
#define K3    (3*DIM)          // split-tripled K = 6144

// ---------------------------------------------------------------------------
// Scratch (allocation-free rule: __device__ globals)
// ---------------------------------------------------------------------------
__device__ float g_qkv[M_TOT * QKV_N];            // fp32 qkv   ~100.7 MB
__device__ __nv_bfloat16 g_x3   [M_TOT * K3];     // 50 MB
__device__ __nv_bfloat16 g_wqkv3[QKV_N * K3];     // 75 MB
__device__ __nv_bfloat16 g_attn3[M_TOT * K3];     // 50 MB (written by attention)
__device__ __nv_bfloat16 g_wout3[DIM   * K3];     // 25 MB

// ---------------------------------------------------------------------------
// mma.sync / ldmatrix / cp.async helpers (baseline sm_80+ PTX, works on sm_100)
// ---------------------------------------------------------------------------
#define LDSM4(r0, r1, r2, r3, addr) \
    asm volatile("ldmatrix.sync.aligned.m8n8.x4.shared.b16 {%0,%1,%2,%3}, [%4];" \
                 : "=r"(r0), "=r"(r1), "=r"(r2), "=r"(r3) : "r"(addr))

#define MMA16816(d0, d1, d2, d3, a0, a1, a2, a3, b0, b1) \
    asm volatile("mma.sync.aligned.m16n8k16.row.col.f32.bf16.bf16.f32 " \
                 "{%0,%1,%2,%3}, {%4,%5,%6,%7}, {%8,%9}, {%0,%1,%2,%3};" \
                 : "+f"(d0), "+f"(d1), "+f"(d2), "+f"(d3) \
                 : "r"(a0), "r"(a1), "r"(a2), "r"(a3), "r"(b0), "r"(b1))

#define CP_ASYNC16(dst_u32, src) \
    asm volatile("cp.async.cg.shared.global [%0], [%1], 16;" :: "r"(dst_u32), "l"(src))
#define CP_COMMIT() asm volatile("cp.async.commit_group;" ::: "memory")
#define CP_WAIT(n)  asm volatile("cp.async.wait_group %0;" :: "n"(n) : "memory")

// ---------------------------------------------------------------------------
// split3: fp32 -> 3-block bf16 split along K.
// dst row stride = 3K:  block0 = hi, block1 = (isA ? lo : hi), block2 = (isA ? hi : lo)
// ---------------------------------------------------------------------------
__global__ __launch_bounds__(256)
void split3_kernel(const float* __restrict__ src, __nv_bfloat16* __restrict__ dst,
                   int K, int isA)
{
    int idx = blockIdx.x * blockDim.x + threadIdx.x;
    int k4cnt = K >> 2;
    int r  = idx / k4cnt;
    int k  = (idx - r * k4cnt) << 2;

    float4 v = *(const float4*)&src[(size_t)r * K + k];
    __nv_bfloat16 h0 = __float2bfloat16(v.x), h1 = __float2bfloat16(v.y);
    __nv_bfloat16 h2 = __float2bfloat16(v.z), h3 = __float2bfloat16(v.w);
    __nv_bfloat16 l0 = __float2bfloat16(v.x - __bfloat162float(h0));
    __nv_bfloat16 l1 = __float2bfloat16(v.y - __bfloat162float(h1));
    __nv_bfloat16 l2 = __float2bfloat16(v.z - __bfloat162float(h2));
    __nv_bfloat16 l3 = __float2bfloat16(v.w - __bfloat162float(h3));

    union { __nv_bfloat16 b[4]; uint2 u; } hi, lo;
    hi.b[0]=h0; hi.b[1]=h1; hi.b[2]=h2; hi.b[3]=h3;
    lo.b[0]=l0; lo.b[1]=l1; lo.b[2]=l2; lo.b[3]=l3;

    size_t base = (size_t)r * (3 * K) + k;
    *(uint2*)&dst[base]         = hi.u;
    *(uint2*)&dst[base + K]     = isA ? lo.u : hi.u;
    *(uint2*)&dst[base + 2 * K] = isA ? hi.u : lo.u;
}

// ---------------------------------------------------------------------------
// mma.sync bf16 GEMM: C[M, ldc](fp32) = A3[M, K3] @ B3[N, K3]^T
// CTA tile 256x128x32, 256 threads (8 warps: 4 m x 2 n, warp tile 64x64).
// 4-stage cp.async circular pipeline (~120 KB dynamic smem), 1 CTA/SM.
// Doubled A-fragment reuse halves LDSM bytes per FLOP vs the 128x128 tile.
// Requires M % 256 == 0 (true: 4096).
// ---------------------------------------------------------------------------
#define BK 32
#define ASTR 40                        // padded row stride in bf16 elems
#define NIT (K3 / BK)                  // 192
#define STAGES 4
#define A_ELEMS (256 * ASTR)           // 10240
#define B_ELEMS (128 * ASTR)           // 5120
#define STAGE_ELEMS (A_ELEMS + B_ELEMS)        // 15360
#define GEMM_SMEM (STAGES * STAGE_ELEMS * 2)   // 122880 bytes

__global__ __launch_bounds__(256, 1)
void gemm_mma_kernel(const __nv_bfloat16* __restrict__ A3,
                     const __nv_bfloat16* __restrict__ B3,
                     float* __restrict__ C, int ldc)
{
    extern __shared__ __nv_bfloat16 smem[];

    const int tid  = threadIdx.x;
    const int wid  = tid >> 5;
    const int lane = tid & 31;
    const int warp_m = wid & 3;          // 0..3  (64-row slice)
    const int warp_n = wid >> 2;         // 0..1  (64-col slice)
    const int m0 = blockIdx.y * 256;
    const int n0 = blockIdx.x * 128;

    const __nv_bfloat16* Abase = A3 + (size_t)m0 * K3;
    const __nv_bfloat16* Bbase = B3 + (size_t)n0 * K3;

    const uint32_t smem_u32 = (uint32_t)__cvta_generic_to_shared(smem);

    // per-thread load slots: 1536 16B chunks per stage (A 1024 + B 512), 6 each
    int rowL[6], segL[6], isBL[6];
    uint32_t soff[6];   // element offset within a stage
    #pragma unroll
    for (int r = 0; r < 6; r++) {
        int chunk = tid + r * 256;
        isBL[r] = (chunk >= 1024);
        int cc  = isBL[r] ? (chunk - 1024) : chunk;
        rowL[r] = cc >> 2;
        segL[r] = cc & 3;
        soff[r] = (isBL[r] ? A_ELEMS : 0) + rowL[r] * ASTR + segL[r] * 8;
    }

    auto load_tile = [&](int it, int st) {
        int k0 = it * BK;
        uint32_t sbase = smem_u32 + (uint32_t)(st * STAGE_ELEMS) * 2;
        #pragma unroll
        for (int r = 0; r < 6; r++) {
            const __nv_bfloat16* src =
                (isBL[r] ? Bbase : Abase) + (size_t)rowL[r] * K3 + k0 + segL[r] * 8;
            CP_ASYNC16(sbase + soff[r] * 2, src);
        }
    };

    float d[4][8][4];
    #pragma unroll
    for (int i = 0; i < 4; i++)
        #pragma unroll
        for (int j = 0; j < 8; j++)
            #pragma unroll
            for (int q = 0; q < 4; q++) d[i][j][q] = 0.f;

    // prologue: fill 3 stages
    #pragma unroll
    for (int p = 0; p < STAGES - 1; p++) {
        load_tile(p, p);
        CP_COMMIT();
    }

    // ldmatrix lane addressing (row = tile_row + lane&15, col = ks + 8*(lane>>4))
    const int lrow = lane & 15;
    const int lcol = (lane >> 4) << 3;

    for (int it = 0; it < NIT; it++) {
        const int cur = it & (STAGES - 1);
        CP_WAIT(STAGES - 2);          // stage `cur` (committed 3 groups ago) done
        __syncthreads();

        const __nv_bfloat16* As = smem + cur * STAGE_ELEMS;
        const __nv_bfloat16* Bs = As + A_ELEMS;

        #pragma unroll
        for (int ks = 0; ks < BK; ks += 16) {
            uint32_t a[4][4], b[4][4];
            #pragma unroll
            for (int i = 0; i < 4; i++) {
                uint32_t addr = (uint32_t)__cvta_generic_to_shared(
                    As + (warp_m * 64 + i * 16 + lrow) * ASTR + ks + lcol);
                LDSM4(a[i][0], a[i][1], a[i][2], a[i][3], addr);
            }
            #pragma unroll
            for (int j = 0; j < 4; j++) {
                uint32_t addr = (uint32_t)__cvta_generic_to_shared(
                    Bs + (warp_n * 64 + j * 16 + lrow) * ASTR + ks + lcol);
                LDSM4(b[j][0], b[j][1], b[j][2], b[j][3], addr);
            }
            #pragma unroll
            for (int i = 0; i < 4; i++) {
                #pragma unroll
                for (int jj = 0; jj < 8; jj++) {
                    uint32_t b0 = b[jj >> 1][(jj & 1)];
                    uint32_t b1 = b[jj >> 1][(jj & 1) + 2];
                    MMA16816(d[i][jj][0], d[i][jj][1], d[i][jj][2], d[i][jj][3],
                             a[i][0], a[i][1], a[i][2], a[i][3], b0, b1);
                }
            }
        }

        // prefetch tile it+3 into the stage just freed at iter it-1
        if (it + STAGES - 1 < NIT)
            load_tile(it + STAGES - 1, (it + STAGES - 1) & (STAGES - 1));
        CP_COMMIT();   // commit unconditionally to keep group counting aligned
    }

    // epilogue: direct fp32 stores (float2 per fragment half)
    const int crow = lane >> 2;
    const int ccol = (lane & 3) * 2;
    #pragma unroll
    for (int i = 0; i < 4; i++) {
        #pragma unroll
        for (int jj = 0; jj < 8; jj++) {
            int m = m0 + warp_m * 64 + i * 16 + crow;
            int n = n0 + warp_n * 64 + jj * 8 + ccol;
            *(float2*)&C[(size_t)m * ldc + n] =
                make_float2(d[i][jj][0], d[i][jj][1]);
            *(float2*)&C[(size_t)(m + 8) * ldc + n] =
                make_float2(d[i][jj][2], d[i][jj][3]);
        }
    }
}

// ---------------------------------------------------------------------------
// RoPE (interleaved pairs) in-place on q,k slices of g_qkv (fp32)
// ---------------------------------------------------------------------------
__global__ __launch_bounds__(256)
void rope_kernel(float* __restrict__ qkv, const float* __restrict__ freqs)
{
    int idx = blockIdx.x * blockDim.x + threadIdx.x;   // < 4096*1024
    int m = idx >> 10;
    int p = idx & 1023;
    int t = m & (SEQ - 1);
    int head = p >> 6;
    int j    = p & 63;

    float ang = freqs[t * HD + 2*j];
    float c = cosf(ang);
    float s = sinf(ang);

    size_t base = (size_t)m * QKV_N + head * HD + 2*j;
    float q0 = qkv[base], q1 = qkv[base + 1];
    qkv[base]     = q0 * c - q1 * s;
    qkv[base + 1] = q1 * c + q0 * s;
    float k0 = qkv[base + DIM], k1 = qkv[base + DIM + 1];
    qkv[base + DIM]     = k0 * c - k1 * s;
    qkv[base + DIM + 1] = k1 * c + k0 * s;
}

// ---------------------------------------------------------------------------
// Causal flash attention, fp32. Epilogue writes the 3-block bf16 split
// layout directly into g_attn3 (hi | lo | hi), fusing the split3 pass.
// ---------------------------------------------------------------------------
__global__ __launch_bounds__(256)
void attn_kernel(const float* __restrict__ qkv, __nv_bfloat16* __restrict__ attn3)
{
    constexpr int BM = 64, BN = 64;
    constexpr int KS = 132;
    constexpr int PS = 68;
    const float scale = 0.08838834764831843f;

    extern __shared__ float sm[];
    float* Qs = sm;
    float* Ks = Qs + BM * KS;
    float* Vs = Ks + BN * KS;
    float* Ps = Vs + BN * KS;

    const int qt   = blockIdx.x;
    const int head = blockIdx.y;
    const int b    = blockIdx.z;
    const int tid  = threadIdx.x;
    const int ty   = tid >> 4;
    const int tx   = tid & 15;

    const size_t rowstride = QKV_N;
    const size_t qoff = (size_t)head * HD;
    const size_t koff = qoff + DIM;
    const size_t voff = qoff + 2 * DIM;

    for (int i = tid; i < BM * 32; i += 256) {
        int r = i >> 5, d4 = (i & 31) * 4;
        size_t g = (size_t)(b * SEQ + qt * BM + r) * rowstride + qoff + d4;
        *(float4*)&Qs[r * KS + d4] = *(const float4*)&qkv[g];
    }

    float acc[4][8];
    #pragma unroll
    for (int r = 0; r < 4; r++)
        #pragma unroll
        for (int j = 0; j < 8; j++) acc[r][j] = 0.f;
    float m_i[4], l_i[4];
    #pragma unroll
    for (int r = 0; r < 4; r++) { m_i[r] = -INFINITY; l_i[r] = 0.f; }

    for (int kt = 0; kt <= qt; kt++) {
        __syncthreads();
        for (int i = tid; i < BN * 32; i += 256) {
            int r = i >> 5, d4 = (i & 31) * 4;
            size_t grow = (size_t)(b * SEQ + kt * BN + r) * rowstride;
            *(float4*)&Ks[r * KS + d4] = *(const float4*)&qkv[grow + koff + d4];
            *(float4*)&Vs[r * KS + d4] = *(const float4*)&qkv[grow + voff + d4];
        }
        __syncthreads();

        float s[4][4];
        #pragma unroll
        for (int r = 0; r < 4; r++)
            #pragma unroll
            for (int j = 0; j < 4; j++) s[r][j] = 0.f;

        for (int d4 = 0; d4 < 32; d4++) {
            float4 kv[4];
            #pragma unroll
            for (int j = 0; j < 4; j++)
                kv[j] = *(float4*)&Ks[(tx + 16*j) * KS + d4*4];
            #pragma unroll
            for (int r = 0; r < 4; r++) {
                float4 qv = *(float4*)&Qs[(ty*4 + r) * KS + d4*4];
                #pragma unroll
                for (int j = 0; j < 4; j++) {
                    s[r][j] = fmaf(qv.x, kv[j].x, s[r][j]);
                    s[r][j] = fmaf(qv.y, kv[j].y, s[r][j]);
                    s[r][j] = fmaf(qv.z, kv[j].z, s[r][j]);
                    s[r][j] = fmaf(qv.w, kv[j].w, s[r][j]);
                }
            }
        }

        #pragma unroll
        for (int r = 0; r < 4; r++) {
            int grow = qt * BM + ty*4 + r;
            float rm = -INFINITY;
            #pragma unroll
            for (int j = 0; j < 4; j++) {
                int gcol = kt * BN + tx + 16*j;
                s[r][j] = (gcol > grow) ? -INFINITY : s[r][j] * scale;
                rm = fmaxf(rm, s[r][j]);
            }
            #pragma unroll
            for (int off = 8; off >= 1; off >>= 1)
                rm = fmaxf(rm, __shfl_xor_sync(0xffffffffu, rm, off));
            float m_new = fmaxf(m_i[r], rm);
            float factor = __expf(m_i[r] - m_new);
            float psum = 0.f;
            #pragma unroll
            for (int j = 0; j < 4; j++) {
                float pv = __expf(s[r][j] - m_new);
                s[r][j] = pv;
                psum += pv;
            }
            #pragma unroll
            for (int off = 8; off >= 1; off >>= 1)
                psum += __shfl_xor_sync(0xffffffffu, psum, off);
            l_i[r] = l_i[r] * factor + psum;
            m_i[r] = m_new;
            #pragma unroll
            for (int j = 0; j < 8; j++) acc[r][j] *= factor;
            #pragma unroll
            for (int j = 0; j < 4; j++)
                Ps[(ty*4 + r) * PS + tx + 16*j] = s[r][j];
        }
        __syncthreads();

        for (int c = 0; c < BN; c++) {
            float4 v0 = *(float4*)&Vs[c * KS + tx*8];
            float4 v1 = *(float4*)&Vs[c * KS + tx*8 + 4];
            #pragma unroll
            for (int r = 0; r < 4; r++) {
                float pv = Ps[(ty*4 + r) * PS + c];
                acc[r][0] = fmaf(pv, v0.x, acc[r][0]);
                acc[r][1] = fmaf(pv, v0.y, acc[r][1]);
                acc[r][2] = fmaf(pv, v0.z, acc[r][2]);
                acc[r][3] = fmaf(pv, v0.w, acc[r][3]);
                acc[r][4] = fmaf(pv, v1.x, acc[r][4]);
                acc[r][5] = fmaf(pv, v1.y, acc[r][5]);
                acc[r][6] = fmaf(pv, v1.z, acc[r][6]);
                acc[r][7] = fmaf(pv, v1.w, acc[r][7]);
            }
        }
    }

    // ---- normalize + fused 3-block bf16 split store: [hi | lo | hi] ----
    #pragma unroll
    for (int r = 0; r < 4; r++) {
        float inv = 1.f / l_i[r];
        union { __nv_bfloat16 b[8]; uint4 u; } hi, lo;
        #pragma unroll
        for (int j = 0; j < 8; j++) {
            float o = acc[r][j] * inv;
            __nv_bfloat16 h = __float2bfloat16(o);
            hi.b[j] = h;
            lo.b[j] = __float2bfloat16(o - __bfloat162float(h));
        }
        size_t row  = (size_t)(b * SEQ + qt * BM + ty*4 + r);
        size_t base = row * (3 * DIM) + head * HD + tx * 8;
        *(uint4*)&attn3[base]           = hi.u;
        *(uint4*)&attn3[base + DIM]     = lo.u;
        *(uint4*)&attn3[base + 2 * DIM] = hi.u;
    }
}

// ---------------------------------------------------------------------------
// launcher
// ---------------------------------------------------------------------------
extern "C" void kernel_launch(void* const* d_in, const int* in_sizes, int n_in,
                              void* d_out, int out_size)
{
    const float* x     = (const float*)d_in[0];   // [2,2048,2048]
    const float* freqs = (const float*)d_in[1];   // [2048,128]
    const float* Wqkv  = (const float*)d_in[2];   // [6144,2048]
    const float* Wout  = (const float*)d_in[3];   // [2048,2048]
    float* out = (float*)d_out;                   // [2,2048,2048]

    float *qkv;
    __nv_bfloat16 *x3, *wqkv3, *attn3, *wout3;
    cudaGetSymbolAddress((void**)&qkv,   g_qkv);
    cudaGetSymbolAddress((void**)&x3,    g_x3);
    cudaGetSymbolAddress((void**)&wqkv3, g_wqkv3);
    cudaGetSymbolAddress((void**)&attn3, g_attn3);
    cudaGetSymbolAddress((void**)&wout3, g_wout3);

    cudaFuncSetAttribute(gemm_mma_kernel,
                         cudaFuncAttributeMaxDynamicSharedMemorySize, GEMM_SMEM);
    const int attn_smem = (3 * 64 * 132 + 64 * 68) * 4;
    cudaFuncSetAttribute(attn_kernel,
                         cudaFuncAttributeMaxDynamicSharedMemorySize, attn_smem);

    // 1) bf16 3-split conversions for stage-1 GEMM
    split3_kernel<<<(M_TOT * (DIM/4)) / 256, 256>>>(x,    x3,    DIM, 1);
    split3_kernel<<<(QKV_N * (DIM/4)) / 256, 256>>>(Wqkv, wqkv3, DIM, 0);

    // 2) QKV projection on tensor cores (256x128 tile, 4-stage pipe)
    gemm_mma_kernel<<<dim3(QKV_N/128, M_TOT/256), 256, GEMM_SMEM>>>(x3, wqkv3, qkv, QKV_N);

    // 3) RoPE in place (fp32)
    rope_kernel<<<(M_TOT * 1024) / 256, 256>>>(qkv, freqs);

    // 4) causal flash attention (fp32) -> writes g_attn3 (fused split)
    attn_kernel<<<dim3(SEQ/64, NH, BATCH), 256, attn_smem>>>(qkv, attn3);

    // 5) weight conversion for stage-2 GEMM
    split3_kernel<<<(DIM * (DIM/4)) / 256, 256>>>(Wout, wout3, DIM, 0);

    // 6) output projection on tensor cores
    gemm_mma_kernel<<<dim3(DIM/128, M_TOT/256), 256, GEMM_SMEM>>>(attn3, wout3, out, DIM);
}

// round 10
// speedup vs baseline: 1.0808x; 1.0808x over previous
#include <cuda_runtime.h>
#include <cuda_bf16.h>
#include <math.h>
#include <stdint.h>

// Problem constants
#define BATCH 2
#define SEQ   2048
#define DIM   2048
#define NH    16
#define HD    128
#define M_TOT (BATCH*SEQ)      // 4096
#define QKV_N (3*DIM)          // 6144
#define K3    (3*DIM)          // split-tripled K = 6144

// ---------------------------------------------------------------------------
// Scratch (allocation-free rule: __device__ globals)
// ---------------------------------------------------------------------------
__device__ float g_qkv[M_TOT * QKV_N];            // fp32 qkv   ~100.7 MB
__device__ __nv_bfloat16 g_x3   [M_TOT * K3];     // 50 MB
__device__ __nv_bfloat16 g_wqkv3[QKV_N * K3];     // 75 MB
__device__ __nv_bfloat16 g_attn3[M_TOT * K3];     // 50 MB (written by attention)
__device__ __nv_bfloat16 g_wout3[DIM   * K3];     // 25 MB

// ---------------------------------------------------------------------------
// mma.sync / ldmatrix / cp.async helpers (baseline sm_80+ PTX, works on sm_100)
// ---------------------------------------------------------------------------
#define LDSM4(r0, r1, r2, r3, addr) \
    asm volatile("ldmatrix.sync.aligned.m8n8.x4.shared.b16 {%0,%1,%2,%3}, [%4];" \
                 : "=r"(r0), "=r"(r1), "=r"(r2), "=r"(r3) : "r"(addr))

#define MMA16816(d0, d1, d2, d3, a0, a1, a2, a3, b0, b1) \
    asm volatile("mma.sync.aligned.m16n8k16.row.col.f32.bf16.bf16.f32 " \
                 "{%0,%1,%2,%3}, {%4,%5,%6,%7}, {%8,%9}, {%0,%1,%2,%3};" \
                 : "+f"(d0), "+f"(d1), "+f"(d2), "+f"(d3) \
                 : "r"(a0), "r"(a1), "r"(a2), "r"(a3), "r"(b0), "r"(b1))

#define CP_ASYNC16(dst_u32, src) \
    asm volatile("cp.async.cg.shared.global [%0], [%1], 16;" :: "r"(dst_u32), "l"(src))
#define CP_COMMIT() asm volatile("cp.async.commit_group;" ::: "memory")
#define CP_WAIT(n)  asm volatile("cp.async.wait_group %0;" :: "n"(n) : "memory")

// ---------------------------------------------------------------------------
// split3: fp32 -> 3-block bf16 split along K.
// dst row stride = 3K:  block0 = hi, block1 = (isA ? lo : hi), block2 = (isA ? hi : lo)
// ---------------------------------------------------------------------------
__global__ __launch_bounds__(256)
void split3_kernel(const float* __restrict__ src, __nv_bfloat16* __restrict__ dst,
                   int K, int isA)
{
    int idx = blockIdx.x * blockDim.x + threadIdx.x;
    int k4cnt = K >> 2;
    int r  = idx / k4cnt;
    int k  = (idx - r * k4cnt) << 2;

    float4 v = *(const float4*)&src[(size_t)r * K + k];
    __nv_bfloat16 h0 = __float2bfloat16(v.x), h1 = __float2bfloat16(v.y);
    __nv_bfloat16 h2 = __float2bfloat16(v.z), h3 = __float2bfloat16(v.w);
    __nv_bfloat16 l0 = __float2bfloat16(v.x - __bfloat162float(h0));
    __nv_bfloat16 l1 = __float2bfloat16(v.y - __bfloat162float(h1));
    __nv_bfloat16 l2 = __float2bfloat16(v.z - __bfloat162float(h2));
    __nv_bfloat16 l3 = __float2bfloat16(v.w - __bfloat162float(h3));

    union { __nv_bfloat16 b[4]; uint2 u; } hi, lo;
    hi.b[0]=h0; hi.b[1]=h1; hi.b[2]=h2; hi.b[3]=h3;
    lo.b[0]=l0; lo.b[1]=l1; lo.b[2]=l2; lo.b[3]=l3;

    size_t base = (size_t)r * (3 * K) + k;
    *(uint2*)&dst[base]         = hi.u;
    *(uint2*)&dst[base + K]     = isA ? lo.u : hi.u;
    *(uint2*)&dst[base + 2 * K] = isA ? hi.u : lo.u;
}

// ---------------------------------------------------------------------------
// mma.sync bf16 GEMM (R8 config, best measured): C = A3 @ B3^T
// Tile 128x128x32, 256 threads (8 warps, 2x4), warp tile 64x32.
// 4-stage cp.async circular pipeline (80 KB dynamic smem), 2 CTAs/SM.
// ---------------------------------------------------------------------------
#define BK 32
#define ASTR 40                    // padded row stride in bf16 elems
#define NIT (K3 / BK)              // 192
#define STAGES 4
#define MAT_ELEMS (128 * ASTR)         // 5120 bf16 per matrix per stage
#define STAGE_ELEMS (2 * MAT_ELEMS)    // A + B
#define GEMM_SMEM (STAGES * STAGE_ELEMS * 2)   // bytes = 81920

__global__ __launch_bounds__(256, 2)
void gemm_mma_kernel(const __nv_bfloat16* __restrict__ A3,
                     const __nv_bfloat16* __restrict__ B3,
                     float* __restrict__ C, int ldc)
{
    extern __shared__ __nv_bfloat16 smem[];

    const int tid  = threadIdx.x;
    const int wid  = tid >> 5;
    const int lane = tid & 31;
    const int warp_m = wid & 1;          // 0..1
    const int warp_n = wid >> 1;         // 0..3
    const int m0 = blockIdx.y * 128;
    const int n0 = blockIdx.x * 128;

    const __nv_bfloat16* Abase = A3 + (size_t)m0 * K3;
    const __nv_bfloat16* Bbase = B3 + (size_t)n0 * K3;

    const uint32_t smem_u32 = (uint32_t)__cvta_generic_to_shared(smem);

    // per-thread load slots: 1024 16B chunks per stage (A 512 + B 512), 4 each
    int rowL[4], segL[4], isBL[4];
    uint32_t soff[4];   // element offset within a stage
    #pragma unroll
    for (int r = 0; r < 4; r++) {
        int chunk = tid + r * 256;
        isBL[r] = chunk >> 9;
        int cc  = chunk & 511;
        rowL[r] = cc >> 2;
        segL[r] = cc & 3;
        soff[r] = isBL[r] * MAT_ELEMS + rowL[r] * ASTR + segL[r] * 8;
    }

    auto load_tile = [&](int it, int st) {
        int k0 = it * BK;
        uint32_t sbase = smem_u32 + (uint32_t)(st * STAGE_ELEMS) * 2;
        #pragma unroll
        for (int r = 0; r < 4; r++) {
            const __nv_bfloat16* src =
                (isBL[r] ? Bbase : Abase) + (size_t)rowL[r] * K3 + k0 + segL[r] * 8;
            CP_ASYNC16(sbase + soff[r] * 2, src);
        }
    };

    float d[4][4][4];
    #pragma unroll
    for (int i = 0; i < 4; i++)
        #pragma unroll
        for (int j = 0; j < 4; j++)
            #pragma unroll
            for (int q = 0; q < 4; q++) d[i][j][q] = 0.f;

    // prologue: fill 3 stages
    #pragma unroll
    for (int p = 0; p < STAGES - 1; p++) {
        load_tile(p, p);
        CP_COMMIT();
    }

    const int lrow = lane & 15;
    const int lcol = (lane >> 4) << 3;

    for (int it = 0; it < NIT; it++) {
        const int cur = it & (STAGES - 1);
        CP_WAIT(STAGES - 2);
        __syncthreads();

        const __nv_bfloat16* As = smem + cur * STAGE_ELEMS;
        const __nv_bfloat16* Bs = As + MAT_ELEMS;

        #pragma unroll
        for (int ks = 0; ks < BK; ks += 16) {
            uint32_t a[4][4], b[2][4];
            #pragma unroll
            for (int i = 0; i < 4; i++) {
                uint32_t addr = (uint32_t)__cvta_generic_to_shared(
                    As + (warp_m * 64 + i * 16 + lrow) * ASTR + ks + lcol);
                LDSM4(a[i][0], a[i][1], a[i][2], a[i][3], addr);
            }
            #pragma unroll
            for (int j = 0; j < 2; j++) {
                uint32_t addr = (uint32_t)__cvta_generic_to_shared(
                    Bs + (warp_n * 32 + j * 16 + lrow) * ASTR + ks + lcol);
                LDSM4(b[j][0], b[j][1], b[j][2], b[j][3], addr);
            }
            #pragma unroll
            for (int i = 0; i < 4; i++) {
                #pragma unroll
                for (int jj = 0; jj < 4; jj++) {
                    uint32_t b0 = b[jj >> 1][(jj & 1)];
                    uint32_t b1 = b[jj >> 1][(jj & 1) + 2];
                    MMA16816(d[i][jj][0], d[i][jj][1], d[i][jj][2], d[i][jj][3],
                             a[i][0], a[i][1], a[i][2], a[i][3], b0, b1);
                }
            }
        }

        if (it + STAGES - 1 < NIT)
            load_tile(it + STAGES - 1, (it + STAGES - 1) & (STAGES - 1));
        CP_COMMIT();
    }

    const int crow = lane >> 2;
    const int ccol = (lane & 3) * 2;
    #pragma unroll
    for (int i = 0; i < 4; i++) {
        #pragma unroll
        for (int jj = 0; jj < 4; jj++) {
            int m = m0 + warp_m * 64 + i * 16 + crow;
            int n = n0 + warp_n * 32 + jj * 8 + ccol;
            *(float2*)&C[(size_t)m * ldc + n] =
                make_float2(d[i][jj][0], d[i][jj][1]);
            *(float2*)&C[(size_t)(m + 8) * ldc + n] =
                make_float2(d[i][jj][2], d[i][jj][3]);
        }
    }
}

// ---------------------------------------------------------------------------
// RoPE (interleaved pairs) in-place on q,k slices of g_qkv (fp32)
// ---------------------------------------------------------------------------
__global__ __launch_bounds__(256)
void rope_kernel(float* __restrict__ qkv, const float* __restrict__ freqs)
{
    int idx = blockIdx.x * blockDim.x + threadIdx.x;   // < 4096*1024
    int m = idx >> 10;
    int p = idx & 1023;
    int t = m & (SEQ - 1);
    int head = p >> 6;
    int j    = p & 63;

    float ang = freqs[t * HD + 2*j];
    float c = cosf(ang);
    float s = sinf(ang);

    size_t base = (size_t)m * QKV_N + head * HD + 2*j;
    float q0 = qkv[base], q1 = qkv[base + 1];
    qkv[base]     = q0 * c - q1 * s;
    qkv[base + 1] = q1 * c + q0 * s;
    float k0 = qkv[base + DIM], k1 = qkv[base + DIM + 1];
    qkv[base + DIM]     = k0 * c - k1 * s;
    qkv[base + DIM + 1] = k1 * c + k0 * s;
}

// ---------------------------------------------------------------------------
// Causal flash attention, fp32. BM=128 (8 rows/thread), BN=64.
// Smem ~166 KB (1 CTA/SM). Blocks processed in reverse qt order so the
// heaviest causal blocks launch first. Epilogue writes the 3-block bf16
// split layout into g_attn3 (hi | lo | hi).
// ---------------------------------------------------------------------------
#define ATTN_SMEM ((128*132 + 64*132 + 64*132 + 128*68) * 4)   // 169984 B

__global__ __launch_bounds__(256)
void attn_kernel(const float* __restrict__ qkv, __nv_bfloat16* __restrict__ attn3)
{
    constexpr int BM = 128, BN = 64;
    constexpr int KS = 132;
    constexpr int PS = 68;
    const float scale = 0.08838834764831843f;

    extern __shared__ float sm[];
    float* Qs = sm;                    // 128*132
    float* Ks = Qs + BM * KS;          // 64*132
    float* Vs = Ks + BN * KS;          // 64*132
    float* Ps = Vs + BN * KS;          // 128*68

    const int qt   = gridDim.x - 1 - blockIdx.x;   // reversed: big blocks first
    const int head = blockIdx.y;
    const int b    = blockIdx.z;
    const int tid  = threadIdx.x;
    const int ty   = tid >> 4;
    const int tx   = tid & 15;

    const size_t rowstride = QKV_N;
    const size_t qoff = (size_t)head * HD;
    const size_t koff = qoff + DIM;
    const size_t voff = qoff + 2 * DIM;

    // load Q tile (128 rows x 128)
    for (int i = tid; i < BM * 32; i += 256) {
        int r = i >> 5, d4 = (i & 31) * 4;
        size_t g = (size_t)(b * SEQ + qt * BM + r) * rowstride + qoff + d4;
        *(float4*)&Qs[r * KS + d4] = *(const float4*)&qkv[g];
    }

    float acc[8][8];
    #pragma unroll
    for (int r = 0; r < 8; r++)
        #pragma unroll
        for (int j = 0; j < 8; j++) acc[r][j] = 0.f;
    float m_i[8], l_i[8];
    #pragma unroll
    for (int r = 0; r < 8; r++) { m_i[r] = -INFINITY; l_i[r] = 0.f; }

    const int ktmax = 2 * qt + 1;
    for (int kt = 0; kt <= ktmax; kt++) {
        __syncthreads();
        for (int i = tid; i < BN * 32; i += 256) {
            int r = i >> 5, d4 = (i & 31) * 4;
            size_t grow = (size_t)(b * SEQ + kt * BN + r) * rowstride;
            *(float4*)&Ks[r * KS + d4] = *(const float4*)&qkv[grow + koff + d4];
            *(float4*)&Vs[r * KS + d4] = *(const float4*)&qkv[grow + voff + d4];
        }
        __syncthreads();

        // ---- S = Q K^T : 8 rows x 4 cols per thread ----
        float s[8][4];
        #pragma unroll
        for (int r = 0; r < 8; r++)
            #pragma unroll
            for (int j = 0; j < 4; j++) s[r][j] = 0.f;

        for (int d4 = 0; d4 < 32; d4++) {
            float4 kv[4];
            #pragma unroll
            for (int j = 0; j < 4; j++)
                kv[j] = *(float4*)&Ks[(tx + 16*j) * KS + d4*4];
            #pragma unroll
            for (int r = 0; r < 8; r++) {
                float4 qv = *(float4*)&Qs[(ty*8 + r) * KS + d4*4];
                #pragma unroll
                for (int j = 0; j < 4; j++) {
                    s[r][j] = fmaf(qv.x, kv[j].x, s[r][j]);
                    s[r][j] = fmaf(qv.y, kv[j].y, s[r][j]);
                    s[r][j] = fmaf(qv.z, kv[j].z, s[r][j]);
                    s[r][j] = fmaf(qv.w, kv[j].w, s[r][j]);
                }
            }
        }

        // ---- scale + causal mask + online softmax ----
        #pragma unroll
        for (int r = 0; r < 8; r++) {
            int grow = qt * BM + ty*8 + r;
            float rm = -INFINITY;
            #pragma unroll
            for (int j = 0; j < 4; j++) {
                int gcol = kt * BN + tx + 16*j;
                s[r][j] = (gcol > grow) ? -INFINITY : s[r][j] * scale;
                rm = fmaxf(rm, s[r][j]);
            }
            #pragma unroll
            for (int off = 8; off >= 1; off >>= 1)
                rm = fmaxf(rm, __shfl_xor_sync(0xffffffffu, rm, off));
            float m_new = fmaxf(m_i[r], rm);
            float factor = __expf(m_i[r] - m_new);
            float psum = 0.f;
            #pragma unroll
            for (int j = 0; j < 4; j++) {
                float pv = __expf(s[r][j] - m_new);
                s[r][j] = pv;
                psum += pv;
            }
            #pragma unroll
            for (int off = 8; off >= 1; off >>= 1)
                psum += __shfl_xor_sync(0xffffffffu, psum, off);
            l_i[r] = l_i[r] * factor + psum;
            m_i[r] = m_new;
            #pragma unroll
            for (int j = 0; j < 8; j++) acc[r][j] *= factor;
            #pragma unroll
            for (int j = 0; j < 4; j++)
                Ps[(ty*8 + r) * PS + tx + 16*j] = s[r][j];
        }
        __syncthreads();

        // ---- O += P V  (8 rows, cols tx*8..+7) ----
        for (int c = 0; c < BN; c++) {
            float4 v0 = *(float4*)&Vs[c * KS + tx*8];
            float4 v1 = *(float4*)&Vs[c * KS + tx*8 + 4];
            #pragma unroll
            for (int r = 0; r < 8; r++) {
                float pv = Ps[(ty*8 + r) * PS + c];
                acc[r][0] = fmaf(pv, v0.x, acc[r][0]);
                acc[r][1] = fmaf(pv, v0.y, acc[r][1]);
                acc[r][2] = fmaf(pv, v0.z, acc[r][2]);
                acc[r][3] = fmaf(pv, v0.w, acc[r][3]);
                acc[r][4] = fmaf(pv, v1.x, acc[r][4]);
                acc[r][5] = fmaf(pv, v1.y, acc[r][5]);
                acc[r][6] = fmaf(pv, v1.z, acc[r][6]);
                acc[r][7] = fmaf(pv, v1.w, acc[r][7]);
            }
        }
    }

    // ---- normalize + fused 3-block bf16 split store: [hi | lo | hi] ----
    #pragma unroll
    for (int r = 0; r < 8; r++) {
        float inv = 1.f / l_i[r];
        union { __nv_bfloat16 b[8]; uint4 u; } hi, lo;
        #pragma unroll
        for (int j = 0; j < 8; j++) {
            float o = acc[r][j] * inv;
            __nv_bfloat16 h = __float2bfloat16(o);
            hi.b[j] = h;
            lo.b[j] = __float2bfloat16(o - __bfloat162float(h));
        }
        size_t row  = (size_t)(b * SEQ + qt * BM + ty*8 + r);
        size_t base = row * (3 * DIM) + head * HD + tx * 8;
        *(uint4*)&attn3[base]           = hi.u;
        *(uint4*)&attn3[base + DIM]     = lo.u;
        *(uint4*)&attn3[base + 2 * DIM] = hi.u;
    }
}

// ---------------------------------------------------------------------------
// launcher
// ---------------------------------------------------------------------------
extern "C" void kernel_launch(void* const* d_in, const int* in_sizes, int n_in,
                              void* d_out, int out_size)
{
    const float* x     = (const float*)d_in[0];   // [2,2048,2048]
    const float* freqs = (const float*)d_in[1];   // [2048,128]
    const float* Wqkv  = (const float*)d_in[2];   // [6144,2048]
    const float* Wout  = (const float*)d_in[3];   // [2048,2048]
    float* out = (float*)d_out;                   // [2,2048,2048]

    float *qkv;
    __nv_bfloat16 *x3, *wqkv3, *attn3, *wout3;
    cudaGetSymbolAddress((void**)&qkv,   g_qkv);
    cudaGetSymbolAddress((void**)&x3,    g_x3);
    cudaGetSymbolAddress((void**)&wqkv3, g_wqkv3);
    cudaGetSymbolAddress((void**)&attn3, g_attn3);
    cudaGetSymbolAddress((void**)&wout3, g_wout3);

    cudaFuncSetAttribute(gemm_mma_kernel,
                         cudaFuncAttributeMaxDynamicSharedMemorySize, GEMM_SMEM);
    cudaFuncSetAttribute(attn_kernel,
                         cudaFuncAttributeMaxDynamicSharedMemorySize, ATTN_SMEM);

    // 1) bf16 3-split conversions for stage-1 GEMM
    split3_kernel<<<(M_TOT * (DIM/4)) / 256, 256>>>(x,    x3,    DIM, 1);
    split3_kernel<<<(QKV_N * (DIM/4)) / 256, 256>>>(Wqkv, wqkv3, DIM, 0);

    // 2) QKV projection on tensor cores (R8 config: 128x128 tile, 2 CTA/SM)
    gemm_mma_kernel<<<dim3(QKV_N/128, M_TOT/128), 256, GEMM_SMEM>>>(x3, wqkv3, qkv, QKV_N);

    // 3) RoPE in place (fp32)
    rope_kernel<<<(M_TOT * 1024) / 256, 256>>>(qkv, freqs);

    // 4) causal flash attention (fp32, BM=128) -> writes g_attn3 (fused split)
    attn_kernel<<<dim3(SEQ/128, NH, BATCH), 256, ATTN_SMEM>>>(qkv, attn3);

    // 5) weight conversion for stage-2 GEMM
    split3_kernel<<<(DIM * (DIM/4)) / 256, 256>>>(Wout, wout3, DIM, 0);

    // 6) output projection on tensor cores
    gemm_mma_kernel<<<dim3(DIM/128, M_TOT/128), 256, GEMM_SMEM>>>(attn3, wout3, out, DIM);
}